// round 1
// baseline (speedup 1.0000x reference)
#include <cuda_runtime.h>

#define T_DIM 4096
#define D_DIM 2048
#define TCH   128
#define NT    (T_DIM / TCH)      /* 32 */
#define BMAX  8
#define NTHREADS 512
#define D4    (D_DIM / 4)        /* 512 */

static __device__ float g_Sx[BMAX * NT * D_DIM];
static __device__ float g_Sq[BMAX * NT * D_DIM];
static __device__ float g_So[BMAX * NT * D_DIM];

__device__ __forceinline__ float tanh_f(float u) {
    // 1 - 2/(e^{2u}+1): saturates cleanly to +-1, exact 0 at 0.
    float e = __expf(2.0f * u);
    return 1.0f - __fdividef(2.0f, e + 1.0f);
}

__device__ __forceinline__ float gelu_f(float x) {
    float x2 = x * x;
    float u = 0.7978845608028654f * (x + 0.044715f * x2 * x);
    return 0.5f * x * (1.0f + tanh_f(u));
}

__global__ __launch_bounds__(NTHREADS) void k_chunksums(const float* __restrict__ x) {
    int tc = blockIdx.x, b = blockIdx.y;
    int d4 = threadIdx.x;
    const float4* xp = reinterpret_cast<const float4*>(x) +
        ((size_t)b * T_DIM + (size_t)tc * TCH) * D4 + d4;

    float4 sx = make_float4(0.f, 0.f, 0.f, 0.f);
    float4 sq = sx, so = sx;

#pragma unroll 4
    for (int i = 0; i < TCH; i++) {
        float4 v = xp[(size_t)i * D4];
        sx.x += v.x; sx.y += v.y; sx.z += v.z; sx.w += v.w;
        sq.x = fmaf(v.x, v.x, sq.x); sq.y = fmaf(v.y, v.y, sq.y);
        sq.z = fmaf(v.z, v.z, sq.z); sq.w = fmaf(v.w, v.w, sq.w);
        so.x += gelu_f(v.x); so.y += gelu_f(v.y);
        so.z += gelu_f(v.z); so.w += gelu_f(v.w);
    }
    size_t o = ((size_t)(b * NT + tc)) * D4 + d4;
    reinterpret_cast<float4*>(g_Sx)[o] = sx;
    reinterpret_cast<float4*>(g_Sq)[o] = sq;
    reinterpret_cast<float4*>(g_So)[o] = so;
}

__global__ void k_prefix(int B) {
    int idx = blockIdx.x * blockDim.x + threadIdx.x;
    if (idx >= B * D_DIM) return;
    int b = idx / D_DIM, d = idx - b * D_DIM;
    float rx = 0.f, rq = 0.f, ro = 0.f;
    for (int tc = 0; tc < NT; tc++) {
        size_t o = ((size_t)(b * NT + tc)) * D_DIM + d;
        float t;
        t = g_Sx[o]; g_Sx[o] = rx; rx += t;
        t = g_Sq[o]; g_Sq[o] = rq; rq += t;
        t = g_So[o]; g_So[o] = ro; ro += t;
    }
}

__global__ __launch_bounds__(NTHREADS) void k_main(const float* __restrict__ x,
                                                   float* __restrict__ out,
                                                   const float* __restrict__ p_lt,
                                                   const float* __restrict__ p_ls,
                                                   const float* __restrict__ p_lw) {
    int tc = blockIdx.x, b = blockIdx.y;
    int tid = threadIdx.x;
    int lane = tid & 31, warp = tid >> 5;

    float tau   = __expf(p_lt[0]);
    float sigma = log1pf(__expf(p_ls[0]));
    float w     = log1pf(__expf(p_lw[0]));

    size_t sidx = ((size_t)(b * NT + tc)) * D4 + tid;
    float4 cx = reinterpret_cast<const float4*>(g_Sx)[sidx];
    float4 cq = reinterpret_cast<const float4*>(g_Sq)[sidx];
    float4 co = reinterpret_cast<const float4*>(g_So)[sidx];

    int t0 = tc * TCH;
    const float4* xp = reinterpret_cast<const float4*>(x) +
        ((size_t)b * T_DIM + t0) * D4 + tid;
    float4* op = reinterpret_cast<float4*>(out) +
        ((size_t)b * T_DIM + t0) * D4 + tid;

    __shared__ float red[16][4];
    __shared__ float gate_sh;

    float4 xv = xp[0];
    for (int i = 0; i < TCH; i++) {
        float4 xn = xv;
        if (i + 1 < TCH) xn = xp[(size_t)(i + 1) * D4];  // prefetch next t

        float invc = 1.0f / (float)(t0 + i + 1);
        float sa = 0.f, sg2 = 0.f, sm2 = 0.f, sgm = 0.f;
        float4 g;

#define COMP(e) { \
        float xe = xv.e; \
        float mu = cx.e * invc; \
        float var = fmaxf(cq.e * invc - mu * mu, 1e-4f); \
        float z = __fdividef(xe - mu, sqrtf(var) + 1e-5f); \
        sa += fabsf(z); \
        float ge = gelu_f(xe); \
        float mo = co.e * invc; \
        sg2 = fmaf(ge, ge, sg2); \
        sm2 = fmaf(mo, mo, sm2); \
        sgm = fmaf(ge, mo, sgm); \
        g.e = ge; \
        cx.e += xe; \
        cq.e = fmaf(xe, xe, cq.e); \
        co.e += ge; }

        COMP(x) COMP(y) COMP(z) COMP(w)
#undef COMP

#pragma unroll
        for (int off = 16; off; off >>= 1) {
            sa  += __shfl_xor_sync(0xffffffffu, sa,  off);
            sg2 += __shfl_xor_sync(0xffffffffu, sg2, off);
            sm2 += __shfl_xor_sync(0xffffffffu, sm2, off);
            sgm += __shfl_xor_sync(0xffffffffu, sgm, off);
        }
        if (lane == 0) {
            red[warp][0] = sa; red[warp][1] = sg2;
            red[warp][2] = sm2; red[warp][3] = sgm;
        }
        __syncthreads();
        if (warp == 0) {
            float a  = (lane < 16) ? red[lane][0] : 0.0f;
            float g2 = (lane < 16) ? red[lane][1] : 0.0f;
            float m2 = (lane < 16) ? red[lane][2] : 0.0f;
            float gm = (lane < 16) ? red[lane][3] : 0.0f;
#pragma unroll
            for (int off = 8; off; off >>= 1) {
                a  += __shfl_xor_sync(0xffffffffu, a,  off);
                g2 += __shfl_xor_sync(0xffffffffu, g2, off);
                m2 += __shfl_xor_sync(0xffffffffu, m2, off);
                gm += __shfl_xor_sync(0xffffffffu, gm, off);
            }
            if (lane == 0) {
                float mask = (t0 + i) >= 1 ? 1.0f : 0.0f;
                float mabz = a * (1.0f / D_DIM) * mask;
                float cosv = gm / (fmaxf(sqrtf(g2), 1e-12f) *
                                   fmaxf(sqrtf(m2), 1e-12f)) * mask;
                float surp = tanh_f(sigma * mabz);
                float gate = __expf(-tau * cosv) * (1.0f + w * surp);
                gate_sh = gate;
            }
        }
        __syncthreads();
        float gate = gate_sh;
        op[(size_t)i * D4] = make_float4(g.x * gate, g.y * gate,
                                         g.z * gate, g.w * gate);
        xv = xn;
    }
}

extern "C" void kernel_launch(void* const* d_in, const int* in_sizes, int n_in,
                              void* d_out, int out_size) {
    const float* x  = (const float*)d_in[0];
    const float* lt = (const float*)d_in[1];
    const float* ls = (const float*)d_in[2];
    const float* lw = (const float*)d_in[3];
    float* out = (float*)d_out;

    int total = in_sizes[0];
    int B = total / (T_DIM * D_DIM);
    if (B < 1) B = 1;
    if (B > BMAX) B = BMAX;

    dim3 grid(NT, B);
    k_chunksums<<<grid, NTHREADS>>>(x);

    int n2 = B * D_DIM;
    k_prefix<<<(n2 + 255) / 256, 256>>>(B);

    k_main<<<grid, NTHREADS>>>(x, out, lt, ls, lw);
}

// round 2
// speedup vs baseline: 1.5520x; 1.5520x over previous
#include <cuda_runtime.h>

#define T_DIM 4096
#define D_DIM 2048
#define TCH   32
#define NT    (T_DIM / TCH)      /* 128 */
#define BMAX  8
#define NTHREADS 512
#define D4    (D_DIM / 4)        /* 512 */

static __device__ float g_Sx[BMAX * NT * D_DIM];
static __device__ float g_Sq[BMAX * NT * D_DIM];
static __device__ float g_So[BMAX * NT * D_DIM];

__device__ __forceinline__ float tanh_fast(float x) {
    float y;
    asm("tanh.approx.f32 %0, %1;" : "=f"(y) : "f"(x));
    return y;
}

__device__ __forceinline__ float gelu_f(float x) {
    float x2 = x * x;
    float u = 0.7978845608028654f * (x + 0.044715f * x2 * x);
    return 0.5f * x * (1.0f + tanh_fast(u));
}

__global__ __launch_bounds__(NTHREADS, 2) void k_chunksums(const float* __restrict__ x) {
    int tc = blockIdx.x, b = blockIdx.y;
    int d4 = threadIdx.x;
    const float4* xp = reinterpret_cast<const float4*>(x) +
        ((size_t)b * T_DIM + (size_t)tc * TCH) * D4 + d4;

    float4 sx = make_float4(0.f, 0.f, 0.f, 0.f);
    float4 sq = sx, so = sx;

#pragma unroll 8
    for (int i = 0; i < TCH; i++) {
        float4 v = xp[(size_t)i * D4];
        sx.x += v.x; sx.y += v.y; sx.z += v.z; sx.w += v.w;
        sq.x = fmaf(v.x, v.x, sq.x); sq.y = fmaf(v.y, v.y, sq.y);
        sq.z = fmaf(v.z, v.z, sq.z); sq.w = fmaf(v.w, v.w, sq.w);
        so.x += gelu_f(v.x); so.y += gelu_f(v.y);
        so.z += gelu_f(v.z); so.w += gelu_f(v.w);
    }
    size_t o = ((size_t)(b * NT + tc)) * D4 + d4;
    reinterpret_cast<float4*>(g_Sx)[o] = sx;
    reinterpret_cast<float4*>(g_Sq)[o] = sq;
    reinterpret_cast<float4*>(g_So)[o] = so;
}

__global__ void k_prefix(int B) {
    int idx = blockIdx.x * blockDim.x + threadIdx.x;
    if (idx >= B * D_DIM) return;
    int b = idx / D_DIM, d = idx - b * D_DIM;
    size_t base = (size_t)b * NT * D_DIM + d;

    float rx = 0.f, rq = 0.f, ro = 0.f;
    float nx = g_Sx[base], nq = g_Sq[base], no = g_So[base];
#pragma unroll 4
    for (int tc = 0; tc < NT; tc++) {
        size_t o = base + (size_t)tc * D_DIM;
        float cxv = nx, cqv = nq, cov = no;
        if (tc + 1 < NT) {
            size_t o2 = o + D_DIM;
            nx = g_Sx[o2]; nq = g_Sq[o2]; no = g_So[o2];
        }
        g_Sx[o] = rx; g_Sq[o] = rq; g_So[o] = ro;
        rx += cxv; rq += cqv; ro += cov;
    }
}

__global__ __launch_bounds__(NTHREADS, 2) void k_main(const float* __restrict__ x,
                                                      float* __restrict__ out,
                                                      const float* __restrict__ p_lt,
                                                      const float* __restrict__ p_ls,
                                                      const float* __restrict__ p_lw) {
    int tc = blockIdx.x, b = blockIdx.y;
    int tid = threadIdx.x;
    int lane = tid & 31, warp = tid >> 5;

    float tau   = __expf(p_lt[0]);
    float sigma = log1pf(__expf(p_ls[0]));
    float w     = log1pf(__expf(p_lw[0]));

    size_t sidx = ((size_t)(b * NT + tc)) * D4 + tid;
    float4 cx = reinterpret_cast<const float4*>(g_Sx)[sidx];
    float4 cq = reinterpret_cast<const float4*>(g_Sq)[sidx];
    float4 co = reinterpret_cast<const float4*>(g_So)[sidx];

    int t0 = tc * TCH;
    const float4* xp = reinterpret_cast<const float4*>(x) +
        ((size_t)b * T_DIM + t0) * D4 + tid;
    float4* op = reinterpret_cast<float4*>(out) +
        ((size_t)b * T_DIM + t0) * D4 + tid;

    __shared__ float red[16][4];
    __shared__ float gate_sh;

    float4 xv = __ldcs(xp);
    for (int i = 0; i < TCH; i++) {
        float4 xn = xv;
        if (i + 1 < TCH) xn = __ldcs(xp + (size_t)(i + 1) * D4);  // prefetch next t

        float invc = 1.0f / (float)(t0 + i + 1);
        float sa = 0.f, sg2 = 0.f, sm2 = 0.f, sgm = 0.f;
        float4 g;

#define COMP(e) { \
        float xe = xv.e; \
        float mu = cx.e * invc; \
        float var = fmaxf(cq.e * invc - mu * mu, 1e-4f); \
        float z = __fdividef(xe - mu, sqrtf(var) + 1e-5f); \
        sa += fabsf(z); \
        float ge = gelu_f(xe); \
        float mo = co.e * invc; \
        sg2 = fmaf(ge, ge, sg2); \
        sm2 = fmaf(mo, mo, sm2); \
        sgm = fmaf(ge, mo, sgm); \
        g.e = ge; \
        cx.e += xe; \
        cq.e = fmaf(xe, xe, cq.e); \
        co.e += ge; }

        COMP(x) COMP(y) COMP(z) COMP(w)
#undef COMP

#pragma unroll
        for (int off = 16; off; off >>= 1) {
            sa  += __shfl_xor_sync(0xffffffffu, sa,  off);
            sg2 += __shfl_xor_sync(0xffffffffu, sg2, off);
            sm2 += __shfl_xor_sync(0xffffffffu, sm2, off);
            sgm += __shfl_xor_sync(0xffffffffu, sgm, off);
        }
        if (lane == 0) {
            red[warp][0] = sa; red[warp][1] = sg2;
            red[warp][2] = sm2; red[warp][3] = sgm;
        }
        __syncthreads();
        if (warp == 0) {
            float a  = (lane < 16) ? red[lane][0] : 0.0f;
            float g2 = (lane < 16) ? red[lane][1] : 0.0f;
            float m2 = (lane < 16) ? red[lane][2] : 0.0f;
            float gm = (lane < 16) ? red[lane][3] : 0.0f;
#pragma unroll
            for (int off = 8; off; off >>= 1) {
                a  += __shfl_xor_sync(0xffffffffu, a,  off);
                g2 += __shfl_xor_sync(0xffffffffu, g2, off);
                m2 += __shfl_xor_sync(0xffffffffu, m2, off);
                gm += __shfl_xor_sync(0xffffffffu, gm, off);
            }
            if (lane == 0) {
                float mask = (t0 + i) >= 1 ? 1.0f : 0.0f;
                float mabz = a * (1.0f / D_DIM) * mask;
                float cosv = gm / (fmaxf(sqrtf(g2), 1e-12f) *
                                   fmaxf(sqrtf(m2), 1e-12f)) * mask;
                float surp = tanh_fast(sigma * mabz);
                float gate = __expf(-tau * cosv) * (1.0f + w * surp);
                gate_sh = gate;
            }
        }
        __syncthreads();
        float gate = gate_sh;
        __stcs(op + (size_t)i * D4, make_float4(g.x * gate, g.y * gate,
                                                g.z * gate, g.w * gate));
        xv = xn;
    }
}

extern "C" void kernel_launch(void* const* d_in, const int* in_sizes, int n_in,
                              void* d_out, int out_size) {
    const float* x  = (const float*)d_in[0];
    const float* lt = (const float*)d_in[1];
    const float* ls = (const float*)d_in[2];
    const float* lw = (const float*)d_in[3];
    float* out = (float*)d_out;

    int total = in_sizes[0];
    int B = total / (T_DIM * D_DIM);
    if (B < 1) B = 1;
    if (B > BMAX) B = BMAX;

    dim3 grid(NT, B);
    k_chunksums<<<grid, NTHREADS>>>(x);

    int n2 = B * D_DIM;
    k_prefix<<<(n2 + 127) / 128, 128>>>(B);

    k_main<<<grid, NTHREADS>>>(x, out, lt, ls, lw);
}

// round 3
// speedup vs baseline: 1.6493x; 1.0627x over previous
#include <cuda_runtime.h>

#define T_DIM 4096
#define D_DIM 2048
#define TCH   32
#define NT    (T_DIM / TCH)      /* 128 */
#define BMAX  8
#define NTHREADS 512
#define D4    (D_DIM / 4)        /* 512 */
#define BT    4                  /* timesteps per batch in k_main */
#define NB    (TCH / BT)         /* 8 batches */

static __device__ float g_Sx[BMAX * NT * D_DIM];
static __device__ float g_Sq[BMAX * NT * D_DIM];
static __device__ float g_So[BMAX * NT * D_DIM];

__device__ __forceinline__ float tanh_fast(float x) {
    float y;
    asm("tanh.approx.f32 %0, %1;" : "=f"(y) : "f"(x));
    return y;
}

__device__ __forceinline__ float gelu_f(float x) {
    float x2 = x * x;
    float u = 0.7978845608028654f * (x + 0.044715f * x2 * x);
    return 0.5f * x * (1.0f + tanh_fast(u));
}

__global__ __launch_bounds__(NTHREADS, 2) void k_chunksums(const float* __restrict__ x) {
    int tc = blockIdx.x, b = blockIdx.y;
    int d4 = threadIdx.x;
    const float4* xp = reinterpret_cast<const float4*>(x) +
        ((size_t)b * T_DIM + (size_t)tc * TCH) * D4 + d4;

    float4 sx = make_float4(0.f, 0.f, 0.f, 0.f);
    float4 sq = sx, so = sx;

#pragma unroll 8
    for (int i = 0; i < TCH; i++) {
        float4 v = __ldcs(xp + (size_t)i * D4);
        sx.x += v.x; sx.y += v.y; sx.z += v.z; sx.w += v.w;
        sq.x = fmaf(v.x, v.x, sq.x); sq.y = fmaf(v.y, v.y, sq.y);
        sq.z = fmaf(v.z, v.z, sq.z); sq.w = fmaf(v.w, v.w, sq.w);
        so.x += gelu_f(v.x); so.y += gelu_f(v.y);
        so.z += gelu_f(v.z); so.w += gelu_f(v.w);
    }
    size_t o = ((size_t)(b * NT + tc)) * D4 + d4;
    reinterpret_cast<float4*>(g_Sx)[o] = sx;
    reinterpret_cast<float4*>(g_Sq)[o] = sq;
    reinterpret_cast<float4*>(g_So)[o] = so;
}

__global__ void k_prefix(int B) {
    int idx = blockIdx.x * blockDim.x + threadIdx.x;
    if (idx >= B * D_DIM) return;
    int b = idx / D_DIM, d = idx - b * D_DIM;
    size_t base = (size_t)b * NT * D_DIM + d;

    float rx = 0.f, rq = 0.f, ro = 0.f;
    float nx = g_Sx[base], nq = g_Sq[base], no = g_So[base];
#pragma unroll 4
    for (int tc = 0; tc < NT; tc++) {
        size_t o = base + (size_t)tc * D_DIM;
        float cxv = nx, cqv = nq, cov = no;
        if (tc + 1 < NT) {
            size_t o2 = o + D_DIM;
            nx = g_Sx[o2]; nq = g_Sq[o2]; no = g_So[o2];
        }
        g_Sx[o] = rx; g_Sq[o] = rq; g_So[o] = ro;
        rx += cxv; rq += cqv; ro += cov;
    }
}

__global__ __launch_bounds__(NTHREADS, 2) void k_main(const float* __restrict__ x,
                                                      float* __restrict__ out,
                                                      const float* __restrict__ p_lt,
                                                      const float* __restrict__ p_ls,
                                                      const float* __restrict__ p_lw) {
    int tc = blockIdx.x, b = blockIdx.y;
    int tid = threadIdx.x;
    int lane = tid & 31, warp = tid >> 5;

    size_t sidx = ((size_t)(b * NT + tc)) * D4 + tid;
    float4 cx = reinterpret_cast<const float4*>(g_Sx)[sidx];
    float4 cq = reinterpret_cast<const float4*>(g_Sq)[sidx];
    float4 co = reinterpret_cast<const float4*>(g_So)[sidx];

    int t0 = tc * TCH;
    const float4* xp = reinterpret_cast<const float4*>(x) +
        ((size_t)b * T_DIM + t0) * D4 + tid;
    float4* op = reinterpret_cast<float4*>(out) +
        ((size_t)b * T_DIM + t0) * D4 + tid;

    __shared__ float4 part[BT][17];      /* [t][warp], padded -> conflict-free */
    __shared__ float  gate_sh[BT];

    for (int bt = 0; bt < NB; bt++) {
        float4 g[BT];
        float4 xr[BT];
        int ib = bt * BT;

        /* issue all BT loads up front (MLP) */
#pragma unroll
        for (int j = 0; j < BT; j++)
            xr[j] = __ldcs(xp + (size_t)(ib + j) * D4);

#pragma unroll
        for (int j = 0; j < BT; j++) {
            float invc = 1.0f / (float)(t0 + ib + j + 1);
            float sa = 0.f, sg2 = 0.f, sm2 = 0.f, sgm = 0.f;
            float4 xv = xr[j];

#define COMP(e) { \
            float xe = xv.e; \
            float mu = cx.e * invc; \
            float var = fmaxf(cq.e * invc - mu * mu, 1e-4f); \
            float z = __fdividef(xe - mu, sqrtf(var) + 1e-5f); \
            sa += fabsf(z); \
            float ge = gelu_f(xe); \
            float mo = co.e * invc; \
            sg2 = fmaf(ge, ge, sg2); \
            sm2 = fmaf(mo, mo, sm2); \
            sgm = fmaf(ge, mo, sgm); \
            g[j].e = ge; \
            cx.e += xe; \
            cq.e = fmaf(xe, xe, cq.e); \
            co.e += ge; }

            COMP(x) COMP(y) COMP(z) COMP(w)
#undef COMP

#pragma unroll
            for (int off = 16; off; off >>= 1) {
                sa  += __shfl_xor_sync(0xffffffffu, sa,  off);
                sg2 += __shfl_xor_sync(0xffffffffu, sg2, off);
                sm2 += __shfl_xor_sync(0xffffffffu, sm2, off);
                sgm += __shfl_xor_sync(0xffffffffu, sgm, off);
            }
            if (lane == 0)
                part[j][warp] = make_float4(sa, sg2, sm2, sgm);
        }
        __syncthreads();

        /* warp 0: lanes 0..15 -> (t = lane>>2, stat = lane&3) */
        if (warp == 0 && lane < BT * 4) {
            int t = lane >> 2, s = lane & 3;
            float v = 0.f;
#pragma unroll
            for (int ww = 0; ww < 16; ww++) {
                const float* p = reinterpret_cast<const float*>(&part[t][ww]);
                v += p[s];
            }
            unsigned m = 0xffffu;
            float a  = __shfl_sync(m, v, (lane & ~3) + 0);
            float g2 = __shfl_sync(m, v, (lane & ~3) + 1);
            float m2 = __shfl_sync(m, v, (lane & ~3) + 2);
            float gm = __shfl_sync(m, v, (lane & ~3) + 3);
            if (s == 0) {
                float tau   = __expf(p_lt[0]);
                float sigma = log1pf(__expf(p_ls[0]));
                float w     = log1pf(__expf(p_lw[0]));
                float mask = (t0 + bt * BT + t) >= 1 ? 1.0f : 0.0f;
                float mabz = a * (1.0f / D_DIM) * mask;
                float cosv = gm / (fmaxf(sqrtf(g2), 1e-12f) *
                                   fmaxf(sqrtf(m2), 1e-12f)) * mask;
                float surp = tanh_fast(sigma * mabz);
                gate_sh[t] = __expf(-tau * cosv) * (1.0f + w * surp);
            }
        }
        __syncthreads();

#pragma unroll
        for (int j = 0; j < BT; j++) {
            float gate = gate_sh[j];
            __stcs(op + (size_t)(ib + j) * D4,
                   make_float4(g[j].x * gate, g[j].y * gate,
                               g[j].z * gate, g[j].w * gate));
        }
    }
}

extern "C" void kernel_launch(void* const* d_in, const int* in_sizes, int n_in,
                              void* d_out, int out_size) {
    const float* x  = (const float*)d_in[0];
    const float* lt = (const float*)d_in[1];
    const float* ls = (const float*)d_in[2];
    const float* lw = (const float*)d_in[3];
    float* out = (float*)d_out;

    int total = in_sizes[0];
    int B = total / (T_DIM * D_DIM);
    if (B < 1) B = 1;
    if (B > BMAX) B = BMAX;

    dim3 grid(NT, B);
    k_chunksums<<<grid, NTHREADS>>>(x);

    int n2 = B * D_DIM;
    k_prefix<<<(n2 + 127) / 128, 128>>>(B);

    k_main<<<grid, NTHREADS>>>(x, out, lt, ls, lw);
}

// round 4
// speedup vs baseline: 1.8070x; 1.0956x over previous
#include <cuda_runtime.h>

#define T_DIM 4096
#define D_DIM 2048
#define TCH   32
#define NT    (T_DIM / TCH)      /* 128 */
#define BMAX  8
#define NTHREADS 512
#define D4    (D_DIM / 4)        /* 512 */
#define BT    4                  /* timesteps per batch in k_main */
#define NB    (TCH / BT)         /* 8 batches */

static __device__ float g_Sx[BMAX * NT * D_DIM];
static __device__ float g_Sq[BMAX * NT * D_DIM];
static __device__ float g_So[BMAX * NT * D_DIM];

__device__ __forceinline__ float tanh_fast(float x) {
    float y;
    asm("tanh.approx.f32 %0, %1;" : "=f"(y) : "f"(x));
    return y;
}

__device__ __forceinline__ float gelu_f(float x) {
    float x2 = x * x;
    float u = 0.7978845608028654f * (x + 0.044715f * x2 * x);
    return 0.5f * x * (1.0f + tanh_fast(u));
}

__global__ __launch_bounds__(NTHREADS, 2) void k_chunksums(const float* __restrict__ x) {
    int tc = blockIdx.x, b = blockIdx.y;
    int d4 = threadIdx.x;
    const float4* xp = reinterpret_cast<const float4*>(x) +
        ((size_t)b * T_DIM + (size_t)tc * TCH) * D4 + d4;

    float4 sx = make_float4(0.f, 0.f, 0.f, 0.f);
    float4 sq = sx, so = sx;

#pragma unroll 8
    for (int i = 0; i < TCH; i++) {
        float4 v = __ldcs(xp + (size_t)i * D4);
        sx.x += v.x; sx.y += v.y; sx.z += v.z; sx.w += v.w;
        sq.x = fmaf(v.x, v.x, sq.x); sq.y = fmaf(v.y, v.y, sq.y);
        sq.z = fmaf(v.z, v.z, sq.z); sq.w = fmaf(v.w, v.w, sq.w);
        so.x += gelu_f(v.x); so.y += gelu_f(v.y);
        so.z += gelu_f(v.z); so.w += gelu_f(v.w);
    }
    size_t o = ((size_t)(b * NT + tc)) * D4 + d4;
    reinterpret_cast<float4*>(g_Sx)[o] = sx;
    reinterpret_cast<float4*>(g_Sq)[o] = sq;
    reinterpret_cast<float4*>(g_So)[o] = so;
}

/* one thread per (array, b, d): 3x the parallelism, 1/3 the serial chain */
__global__ void k_prefix(int B) {
    int idx = blockIdx.x * blockDim.x + threadIdx.x;
    int bd = B * D_DIM;
    if (idx >= 3 * bd) return;
    int part = idx / bd;
    int rem = idx - part * bd;

    float* arr = (part == 0) ? g_Sx : (part == 1) ? g_Sq : g_So;
    size_t base = (size_t)(rem / D_DIM) * NT * D_DIM + (rem % D_DIM);

    float r = 0.f;
    float nv = arr[base];
#pragma unroll 4
    for (int tc = 0; tc < NT; tc++) {
        size_t o = base + (size_t)tc * D_DIM;
        float cur = nv;
        if (tc + 1 < NT) nv = arr[o + D_DIM];
        arr[o] = r;
        r += cur;
    }
}

__global__ __launch_bounds__(NTHREADS, 2) void k_main(const float* __restrict__ x,
                                                      float* __restrict__ out,
                                                      const float* __restrict__ p_lt,
                                                      const float* __restrict__ p_ls,
                                                      const float* __restrict__ p_lw) {
    int tc = blockIdx.x, b = blockIdx.y;
    int tid = threadIdx.x;
    int lane = tid & 31, warp = tid >> 5;

    size_t sidx = ((size_t)(b * NT + tc)) * D4 + tid;
    float4 cx = reinterpret_cast<const float4*>(g_Sx)[sidx];
    float4 cq = reinterpret_cast<const float4*>(g_Sq)[sidx];
    float4 co = reinterpret_cast<const float4*>(g_So)[sidx];

    int t0 = tc * TCH;
    const float4* xp = reinterpret_cast<const float4*>(x) +
        ((size_t)b * T_DIM + t0) * D4 + tid;
    float4* op = reinterpret_cast<float4*>(out) +
        ((size_t)b * T_DIM + t0) * D4 + tid;

    __shared__ float4 part[BT][17];      /* [t][warp], padded -> conflict-free */
    __shared__ float  gate_sh[BT];

    for (int bt = 0; bt < NB; bt++) {
        float4 v[BT];                    /* holds x on load, gelu(x) after stats */
        int ib = bt * BT;

        /* issue all BT loads up front (MLP) */
#pragma unroll
        for (int j = 0; j < BT; j++)
            v[j] = __ldcs(xp + (size_t)(ib + j) * D4);

#pragma unroll
        for (int j = 0; j < BT; j++) {
            float invc = 1.0f / (float)(t0 + ib + j + 1);
            float sa = 0.f, sg2 = 0.f, sm2 = 0.f, sgm = 0.f;

#define COMP(e) { \
            float xe = v[j].e; \
            float mu = cx.e * invc; \
            float var = fmaxf(cq.e * invc - mu * mu, 1e-4f); \
            float z = __fdividef(xe - mu, sqrtf(var) + 1e-5f); \
            sa += fabsf(z); \
            float ge = gelu_f(xe); \
            float mo = co.e * invc; \
            sg2 = fmaf(ge, ge, sg2); \
            sm2 = fmaf(mo, mo, sm2); \
            sgm = fmaf(ge, mo, sgm); \
            cx.e += xe; \
            cq.e = fmaf(xe, xe, cq.e); \
            co.e += ge; \
            v[j].e = ge; }

            COMP(x) COMP(y) COMP(z) COMP(w)
#undef COMP

#pragma unroll
            for (int off = 16; off; off >>= 1) {
                sa  += __shfl_xor_sync(0xffffffffu, sa,  off);
                sg2 += __shfl_xor_sync(0xffffffffu, sg2, off);
                sm2 += __shfl_xor_sync(0xffffffffu, sm2, off);
                sgm += __shfl_xor_sync(0xffffffffu, sgm, off);
            }
            if (lane == 0)
                part[j][warp] = make_float4(sa, sg2, sm2, sgm);
        }
        __syncthreads();

        /* warp 0: lanes 0..15 -> (t = lane>>2, stat = lane&3) */
        if (warp == 0 && lane < BT * 4) {
            int t = lane >> 2, s = lane & 3;
            float vv = 0.f;
#pragma unroll
            for (int ww = 0; ww < 16; ww++) {
                const float* p = reinterpret_cast<const float*>(&part[t][ww]);
                vv += p[s];
            }
            unsigned m = 0xffffu;
            float a  = __shfl_sync(m, vv, (lane & ~3) + 0);
            float g2 = __shfl_sync(m, vv, (lane & ~3) + 1);
            float m2 = __shfl_sync(m, vv, (lane & ~3) + 2);
            float gm = __shfl_sync(m, vv, (lane & ~3) + 3);
            if (s == 0) {
                float tau   = __expf(p_lt[0]);
                float sigma = log1pf(__expf(p_ls[0]));
                float w     = log1pf(__expf(p_lw[0]));
                float mask = (t0 + bt * BT + t) >= 1 ? 1.0f : 0.0f;
                float mabz = a * (1.0f / D_DIM) * mask;
                float cosv = gm / (fmaxf(sqrtf(g2), 1e-12f) *
                                   fmaxf(sqrtf(m2), 1e-12f)) * mask;
                float surp = tanh_fast(sigma * mabz);
                gate_sh[t] = __expf(-tau * cosv) * (1.0f + w * surp);
            }
        }
        __syncthreads();

#pragma unroll
        for (int j = 0; j < BT; j++) {
            float gate = gate_sh[j];
            __stcs(op + (size_t)(ib + j) * D4,
                   make_float4(v[j].x * gate, v[j].y * gate,
                               v[j].z * gate, v[j].w * gate));
        }
    }
}

extern "C" void kernel_launch(void* const* d_in, const int* in_sizes, int n_in,
                              void* d_out, int out_size) {
    const float* x  = (const float*)d_in[0];
    const float* lt = (const float*)d_in[1];
    const float* ls = (const float*)d_in[2];
    const float* lw = (const float*)d_in[3];
    float* out = (float*)d_out;

    int total = in_sizes[0];
    int B = total / (T_DIM * D_DIM);
    if (B < 1) B = 1;
    if (B > BMAX) B = BMAX;

    dim3 grid(NT, B);
    k_chunksums<<<grid, NTHREADS>>>(x);

    int n2 = 3 * B * D_DIM;
    k_prefix<<<(n2 + 255) / 256, 256>>>(B);

    k_main<<<grid, NTHREADS>>>(x, out, lt, ls, lw);
}

// round 5
// speedup vs baseline: 2.0314x; 1.1242x over previous
#include <cuda_runtime.h>

#define T_DIM 4096
#define D_DIM 2048
#define TCH   32
#define NT    (T_DIM / TCH)      /* 128 */
#define BMAX  8
#define NTHREADS 512
#define D4    (D_DIM / 4)        /* 512 */
#define BT    4                  /* timesteps per batch in k_main */
#define NB    (TCH / BT)         /* 8 batches */

static __device__ float g_Sx[BMAX * NT * D_DIM];
static __device__ float g_Sq[BMAX * NT * D_DIM];
static __device__ float g_So[BMAX * NT * D_DIM];

__device__ __forceinline__ float tanh_fast(float x) {
    float y;
    asm("tanh.approx.f32 %0, %1;" : "=f"(y) : "f"(x));
    return y;
}

__device__ __forceinline__ float gelu_f(float x) {
    float x2 = x * x;
    float u = x * fmaf(0.035677408136f, x2, 0.7978845608028654f);
    float hx = 0.5f * x;
    return fmaf(hx, tanh_fast(u), hx);
}

__global__ __launch_bounds__(NTHREADS, 2) void k_chunksums(const float* __restrict__ x) {
    int tc = blockIdx.x, b = blockIdx.y;
    int d4 = threadIdx.x;
    const float4* xp = reinterpret_cast<const float4*>(x) +
        ((size_t)b * T_DIM + (size_t)tc * TCH) * D4 + d4;

    float4 sx = make_float4(0.f, 0.f, 0.f, 0.f);
    float4 sq = sx, so = sx;

#pragma unroll 8
    for (int i = 0; i < TCH; i++) {
        float4 v = __ldcs(xp + (size_t)i * D4);
        sx.x += v.x; sx.y += v.y; sx.z += v.z; sx.w += v.w;
        sq.x = fmaf(v.x, v.x, sq.x); sq.y = fmaf(v.y, v.y, sq.y);
        sq.z = fmaf(v.z, v.z, sq.z); sq.w = fmaf(v.w, v.w, sq.w);
        so.x += gelu_f(v.x); so.y += gelu_f(v.y);
        so.z += gelu_f(v.z); so.w += gelu_f(v.w);
    }
    size_t o = ((size_t)(b * NT + tc)) * D4 + d4;
    reinterpret_cast<float4*>(g_Sx)[o] = sx;
    reinterpret_cast<float4*>(g_Sq)[o] = sq;
    reinterpret_cast<float4*>(g_So)[o] = so;
}

/* one thread per (array, b, d) */
__global__ void k_prefix(int B) {
    int idx = blockIdx.x * blockDim.x + threadIdx.x;
    int bd = B * D_DIM;
    if (idx >= 3 * bd) return;
    int part = idx / bd;
    int rem = idx - part * bd;

    float* arr = (part == 0) ? g_Sx : (part == 1) ? g_Sq : g_So;
    size_t base = (size_t)(rem / D_DIM) * NT * D_DIM + (rem % D_DIM);

    float r = 0.f;
    float nv = arr[base];
#pragma unroll 4
    for (int tc = 0; tc < NT; tc++) {
        size_t o = base + (size_t)tc * D_DIM;
        float cur = nv;
        if (tc + 1 < NT) nv = arr[o + D_DIM];
        arr[o] = r;
        r += cur;
    }
}

__global__ __launch_bounds__(NTHREADS, 2) void k_main(const float* __restrict__ x,
                                                      float* __restrict__ out,
                                                      const float* __restrict__ p_lt,
                                                      const float* __restrict__ p_ls,
                                                      const float* __restrict__ p_lw) {
    int tc = blockIdx.x, b = blockIdx.y;
    int tid = threadIdx.x;
    int lane = tid & 31, warp = tid >> 5;

    float tau   = __expf(p_lt[0]);
    float sigma = log1pf(__expf(p_ls[0]));
    float w     = log1pf(__expf(p_lw[0]));

    size_t sidx = ((size_t)(b * NT + tc)) * D4 + tid;
    float4 cx = reinterpret_cast<const float4*>(g_Sx)[sidx];
    float4 cq = reinterpret_cast<const float4*>(g_Sq)[sidx];
    float4 co = reinterpret_cast<const float4*>(g_So)[sidx];

    int t0 = tc * TCH;
    const float4* xp = reinterpret_cast<const float4*>(x) +
        ((size_t)b * T_DIM + t0) * D4 + tid;
    float4* op = reinterpret_cast<float4*>(out) +
        ((size_t)b * T_DIM + t0) * D4 + tid;

    __shared__ float4 part[2][BT][17];   /* double-buffered, padded */

    float4 va[BT], vb[BT];

#pragma unroll
    for (int j = 0; j < BT; j++)
        va[j] = __ldcs(xp + (size_t)j * D4);

#define LOADB(V, IB) { \
    _Pragma("unroll") \
    for (int j = 0; j < BT; j++) \
        V[j] = __ldcs(xp + (size_t)((IB) + j) * D4); }

#define PROCESS(V, IB, PB) { \
    _Pragma("unroll") \
    for (int j = 0; j < BT; j++) { \
        float invc = __fdividef(1.0f, (float)(t0 + (IB) + j + 1)); \
        float sa = 0.f, sg2 = 0.f, sm2 = 0.f, sgm = 0.f; \
        COMP(V, j, x) COMP(V, j, y) COMP(V, j, z) COMP(V, j, w) \
        _Pragma("unroll") \
        for (int off = 16; off; off >>= 1) { \
            sa  += __shfl_xor_sync(0xffffffffu, sa,  off); \
            sg2 += __shfl_xor_sync(0xffffffffu, sg2, off); \
            sm2 += __shfl_xor_sync(0xffffffffu, sm2, off); \
            sgm += __shfl_xor_sync(0xffffffffu, sgm, off); \
        } \
        if (lane == 0) part[PB][j][warp] = make_float4(sa, sg2, sm2, sgm); \
    } \
    __syncthreads(); \
    float gate = 0.f; \
    { \
        int tt = lane >> 2, ss = lane & 3; \
        float vv = 0.f; \
        if (lane < 16) { \
            _Pragma("unroll") \
            for (int ww = 0; ww < 16; ww++) \
                vv += reinterpret_cast<const float*>(&part[PB][tt][ww])[ss]; \
        } \
        unsigned m = 0xffffffffu; \
        float a  = __shfl_sync(m, vv, (lane & ~3) + 0); \
        float g2 = __shfl_sync(m, vv, (lane & ~3) + 1); \
        float m2 = __shfl_sync(m, vv, (lane & ~3) + 2); \
        float gm = __shfl_sync(m, vv, (lane & ~3) + 3); \
        if (ss == 0) { \
            float mask = (t0 + (IB) + tt) >= 1 ? 1.0f : 0.0f; \
            float mabz = a * (1.0f / D_DIM) * mask; \
            float cosv = gm / (fmaxf(sqrtf(g2), 1e-12f) * \
                               fmaxf(sqrtf(m2), 1e-12f)) * mask; \
            float surp = tanh_fast(sigma * mabz); \
            gate = __expf(-tau * cosv) * (1.0f + w * surp); \
        } \
    } \
    _Pragma("unroll") \
    for (int j = 0; j < BT; j++) { \
        float gj = __shfl_sync(0xffffffffu, gate, j * 4); \
        __stcs(op + (size_t)((IB) + j) * D4, \
               make_float4(V[j].x * gj, V[j].y * gj, V[j].z * gj, V[j].w * gj)); \
    } }

#define COMP(V, j, e) { \
    float xe = V[j].e; \
    float mu = cx.e * invc; \
    float var = fmaxf(fmaf(-mu, mu, cq.e * invc), 1e-4f); \
    float r = rsqrtf(var); \
    float inv = r * fmaf(-1e-5f, r, 1.0f); \
    sa += fabsf((xe - mu) * inv); \
    float ge = gelu_f(xe); \
    sg2 = fmaf(ge, ge, sg2); \
    sm2 = fmaf(co.e, co.e, sm2); \
    sgm = fmaf(ge, co.e, sgm); \
    cx.e += xe; \
    cq.e = fmaf(xe, xe, cq.e); \
    co.e += ge; \
    V[j].e = ge; }

    for (int bt = 0; bt < NB; bt += 2) {
        int ib0 = bt * BT;
        LOADB(vb, ib0 + BT);
        PROCESS(va, ib0, 0);
        if (bt + 2 < NB) LOADB(va, ib0 + 2 * BT);
        PROCESS(vb, ib0 + BT, 1);
    }

#undef COMP
#undef PROCESS
#undef LOADB
}

extern "C" void kernel_launch(void* const* d_in, const int* in_sizes, int n_in,
                              void* d_out, int out_size) {
    const float* x  = (const float*)d_in[0];
    const float* lt = (const float*)d_in[1];
    const float* ls = (const float*)d_in[2];
    const float* lw = (const float*)d_in[3];
    float* out = (float*)d_out;

    int total = in_sizes[0];
    int B = total / (T_DIM * D_DIM);
    if (B < 1) B = 1;
    if (B > BMAX) B = BMAX;

    dim3 grid(NT, B);
    k_chunksums<<<grid, NTHREADS>>>(x);

    int n2 = 3 * B * D_DIM;
    k_prefix<<<(n2 + 255) / 256, 256>>>(B);

    k_main<<<grid, NTHREADS>>>(x, out, lt, ls, lw);
}